// round 5
// baseline (speedup 1.0000x reference)
#include <cuda_runtime.h>

#define TLEN 8192
#define TILE 2048            // outputs per block
#define NTHR 256             // 8 outputs per thread
#define NEO  2056            // 2054 act pairs used + float4 pad

// snake(u) = u + ib*sin^2(a*u) = (u + c0) - c0*cos(2a*u),  c0 = ib/2
__device__ __forceinline__ float snake(float u, float a2, float c0) {
    return fmaf(-c0, __cosf(u * a2), u + c0);
}

__global__ void __launch_bounds__(NTHR, 4)
act1d_kernel(const float* __restrict__ x,
             const float* __restrict__ upf,
             const float* __restrict__ dnf,
             const float* __restrict__ alpha,
             const float* __restrict__ beta,
             float* __restrict__ out,
             int nch)
{
    __shared__ __align__(16) float Es[NEO];
    __shared__ __align__(16) float Os[NEO];

    const int tid = threadIdx.x;
    const int row = blockIdx.y;
    const int m0  = blockIdx.x * TILE;
    const int ch  = row % nch;
    const int b   = 8 * tid;                     // first owned pair / output

    const float a2 = 2.0f * __expf(__ldg(alpha + ch));
    const float c0 = 0.5f * __fdividef(1.0f, __expf(__ldg(beta + ch)) + 1e-9f);

    const float* xrow = x + (size_t)row * TLEN;
    const bool first = (m0 == 0);
    const bool last  = (m0 + TILE == TLEN);

    // ---- x for owned pairs: xv[j] = x_clamped[m0 + b - 8 + j], j=0..15 ----
    // used: E[q=b+k] taps xv[k+2..k+7], O[q=b+k] taps xv[k+3..k+8], k=0..7 -> xv[2..15]
    float xv[16];
    if (!(first && tid < 32)) {                  // warp-uniform branch
        const float4* s = (const float4*)(xrow + (m0 + b - 8));
        float4 v0 = s[0], v1 = s[1], v2 = s[2], v3 = s[3];
        xv[0] =v0.x; xv[1] =v0.y; xv[2] =v0.z; xv[3] =v0.w;
        xv[4] =v1.x; xv[5] =v1.y; xv[6] =v1.z; xv[7] =v1.w;
        xv[8] =v2.x; xv[9] =v2.y; xv[10]=v2.z; xv[11]=v2.w;
        xv[12]=v3.x; xv[13]=v3.y; xv[14]=v3.z; xv[15]=v3.w;
    } else {                                     // first block, warp 0: clamp low
        const int xb = b - 8;
        #pragma unroll
        for (int j = 0; j < 16; j++) {
            int g = xb + j;
            xv[j] = xrow[g < 0 ? 0 : g];
        }
    }

    float uf2[12];
    {
        const float4* u4 = (const float4*)upf;
        float4 u0 = __ldg(u4), u1 = __ldg(u4 + 1), u2 = __ldg(u4 + 2);
        uf2[0] = 2.f*u0.x; uf2[1] = 2.f*u0.y; uf2[2]  = 2.f*u0.z; uf2[3]  = 2.f*u0.w;
        uf2[4] = 2.f*u1.x; uf2[5] = 2.f*u1.y; uf2[6]  = 2.f*u1.z; uf2[7]  = 2.f*u1.w;
        uf2[8] = 2.f*u2.x; uf2[9] = 2.f*u2.y; uf2[10] = 2.f*u2.z; uf2[11] = 2.f*u2.w;
    }

    // ---- phase 1: 8 (E,O) act pairs ----
    float ev[8], ov[8];
    #pragma unroll
    for (int k = 0; k < 8; k++) {
        float ue =      uf2[11] * xv[k + 2];
        ue = fmaf(uf2[9],  xv[k + 3], ue);
        ue = fmaf(uf2[7],  xv[k + 4], ue);
        ue = fmaf(uf2[5],  xv[k + 5], ue);
        ue = fmaf(uf2[3],  xv[k + 6], ue);
        ue = fmaf(uf2[1],  xv[k + 7], ue);
        float uo =      uf2[10] * xv[k + 3];
        uo = fmaf(uf2[8],  xv[k + 4], uo);
        uo = fmaf(uf2[6],  xv[k + 5], uo);
        uo = fmaf(uf2[4],  xv[k + 6], uo);
        uo = fmaf(uf2[2],  xv[k + 7], uo);
        uo = fmaf(uf2[0],  xv[k + 8], uo);
        ev[k] = snake(ue, a2, c0);
        ov[k] = snake(uo, a2, c0);
    }

    // first block, tid 0: act indices t<0 clamp to act[0] == E[3]
    if (first && tid == 0) {
        ev[0] = ev[1] = ev[2] = ev[3];
        ov[0] = ov[1] = ov[2] = ev[3];
    }

    *(float4*)(Es + b)     = make_float4(ev[0], ev[1], ev[2], ev[3]);
    *(float4*)(Es + b + 4) = make_float4(ev[4], ev[5], ev[6], ev[7]);
    *(float4*)(Os + b)     = make_float4(ov[0], ov[1], ov[2], ov[3]);
    *(float4*)(Os + b + 4) = make_float4(ov[4], ov[5], ov[6], ov[7]);

    // halo pairs q = TILE..TILE+5 (scalar, clamped global reads)
    if (tid < 6) {
        const int q = TILE + tid;
        float xh[7];
        #pragma unroll
        for (int j = 0; j < 7; j++) {
            int g = m0 + q - 6 + j;
            xh[j] = xrow[g > TLEN - 1 ? TLEN - 1 : g];
        }
        float ue =      uf2[11] * xh[0];
        ue = fmaf(uf2[9],  xh[1], ue);
        ue = fmaf(uf2[7],  xh[2], ue);
        ue = fmaf(uf2[5],  xh[3], ue);
        ue = fmaf(uf2[3],  xh[4], ue);
        ue = fmaf(uf2[1],  xh[5], ue);
        float uo =      uf2[10] * xh[1];
        uo = fmaf(uf2[8],  xh[2], uo);
        uo = fmaf(uf2[6],  xh[3], uo);
        uo = fmaf(uf2[4],  xh[4], uo);
        uo = fmaf(uf2[2],  xh[5], uo);
        uo = fmaf(uf2[0],  xh[6], uo);
        float Eh = snake(ue, a2, c0);
        float Oh = snake(uo, a2, c0);
        if (last) {
            // t > 16383 clamps to act[16383] == O[TILE+2]
            if (tid == 2) {
                Es[q] = Eh; Os[q] = Oh;
                Es[TILE+3] = Oh; Es[TILE+4] = Oh; Es[TILE+5] = Oh;
                Os[TILE+3] = Oh; Os[TILE+4] = Oh; Os[TILE+5] = Oh;
            } else if (tid < 2) {
                Es[q] = Eh; Os[q] = Oh;
            }
        } else {
            Es[q] = Eh; Os[q] = Oh;
        }
    }
    __syncthreads();

    // ---- phase 2: out[m0+b+k] = sum_r df[2r]*o[k+r] + df[2r+1]*e[k+r+1], k=0..7 ----
    {
        float df[12];
        {
            const float4* d4 = (const float4*)dnf;
            float4 d0 = __ldg(d4), d1 = __ldg(d4 + 1), d2 = __ldg(d4 + 2);
            df[0] = d0.x; df[1] = d0.y; df[2]  = d0.z; df[3]  = d0.w;
            df[4] = d1.x; df[5] = d1.y; df[6]  = d1.z; df[7]  = d1.w;
            df[8] = d2.x; df[9] = d2.y; df[10] = d2.z; df[11] = d2.w;
        }

        float o[13], e[14];
        #pragma unroll
        for (int k = 0; k < 8; k++) o[k] = ov[k];
        #pragma unroll
        for (int k = 1; k < 8; k++) e[k] = ev[k];
        float4 o8 = *(const float4*)(Os + b + 8);
        o[8] = o8.x; o[9] = o8.y; o[10] = o8.z; o[11] = o8.w;
        o[12] = Os[b + 12];
        float4 e8 = *(const float4*)(Es + b + 8);
        e[8] = e8.x; e[9] = e8.y; e[10] = e8.z; e[11] = e8.w;
        float2 e12 = *(const float2*)(Es + b + 12);
        e[12] = e12.x; e[13] = e12.y;

        float4 r0, r1;
        #pragma unroll
        for (int k = 0; k < 8; k++) {
            float r = df[0] * o[k];
            r = fmaf(df[1],  e[k + 1], r);
            r = fmaf(df[2],  o[k + 1], r);
            r = fmaf(df[3],  e[k + 2], r);
            r = fmaf(df[4],  o[k + 2], r);
            r = fmaf(df[5],  e[k + 3], r);
            r = fmaf(df[6],  o[k + 3], r);
            r = fmaf(df[7],  e[k + 4], r);
            r = fmaf(df[8],  o[k + 4], r);
            r = fmaf(df[9],  e[k + 5], r);
            r = fmaf(df[10], o[k + 5], r);
            r = fmaf(df[11], e[k + 6], r);
            if (k < 4) ((float*)&r0)[k] = r;
            else       ((float*)&r1)[k - 4] = r;
        }
        float* op = out + (size_t)row * TLEN + m0 + b;
        *(float4*)op       = r0;
        *(float4*)(op + 4) = r1;
    }
}

extern "C" void kernel_launch(void* const* d_in, const int* in_sizes, int n_in,
                              void* d_out, int out_size) {
    const float* x     = (const float*)d_in[0];
    const float* upf   = (const float*)d_in[1];
    const float* dnf   = (const float*)d_in[2];
    const float* alpha = (const float*)d_in[3];
    const float* beta  = (const float*)d_in[4];
    float* out = (float*)d_out;

    const int rows = in_sizes[0] / TLEN;   // B*C
    const int nch  = in_sizes[3];          // C

    dim3 grid(TLEN / TILE, rows);
    act1d_kernel<<<grid, NTHR>>>(x, upf, dnf, alpha, beta, out, nch);
}

// round 6
// speedup vs baseline: 1.2218x; 1.2218x over previous
#include <cuda_runtime.h>

#define TLEN 8192
#define TILE 2048            // outputs per block
#define NTHR 256             // 2 chunks of 4 outputs per thread
#define NEO  2056            // 2054 act pairs used + pad

// snake(u) = u + ib*sin^2(a*u) = (u + c0) - c0*cos(2a*u),  c0 = ib/2
__device__ __forceinline__ float snake(float u, float a2, float c0) {
    return fmaf(-c0, __cosf(u * a2), u + c0);
}

__global__ void __launch_bounds__(NTHR, 5)
act1d_kernel(const float* __restrict__ x,
             const float* __restrict__ upf,
             const float* __restrict__ dnf,
             const float* __restrict__ alpha,
             const float* __restrict__ beta,
             float* __restrict__ out,
             int nch)
{
    __shared__ __align__(16) float Es[NEO];
    __shared__ __align__(16) float Os[NEO];

    const int tid = threadIdx.x;
    const int row = blockIdx.y;
    const int m0  = blockIdx.x * TILE;
    const int ch  = row % nch;
    const int bA  = 4 * tid;             // chunk A pairs/outputs
    const int bB  = 1024 + 4 * tid;      // chunk B pairs/outputs

    const float a2 = 2.0f * __expf(__ldg(alpha + ch));
    const float c0 = 0.5f * __fdividef(1.0f, __expf(__ldg(beta + ch)) + 1e-9f);

    const float* xrow = x + (size_t)row * TLEN;
    const bool first = (m0 == 0);
    const bool last  = (m0 + TILE == TLEN);

    float uf2[12];
    {
        const float4* u4 = (const float4*)upf;
        float4 u0 = __ldg(u4), u1 = __ldg(u4 + 1), u2 = __ldg(u4 + 2);
        uf2[0] = 2.f*u0.x; uf2[1] = 2.f*u0.y; uf2[2]  = 2.f*u0.z; uf2[3]  = 2.f*u0.w;
        uf2[4] = 2.f*u1.x; uf2[5] = 2.f*u1.y; uf2[6]  = 2.f*u1.z; uf2[7]  = 2.f*u1.w;
        uf2[8] = 2.f*u2.x; uf2[9] = 2.f*u2.y; uf2[10] = 2.f*u2.z; uf2[11] = 2.f*u2.w;
    }

    float evA[4], ovA[4], evB[4], ovB[4];

    // ================= phase 1, chunk A (pairs bA..bA+3) =================
    {
        float xv[12];
        if (!(first && tid < 32)) {              // warp-uniform
            const float4* s = (const float4*)(xrow + (m0 + bA - 8));
            float4 v0 = s[0], v1 = s[1], v2 = s[2];
            xv[0]=v0.x; xv[1]=v0.y; xv[2] =v0.z; xv[3] =v0.w;
            xv[4]=v1.x; xv[5]=v1.y; xv[6] =v1.z; xv[7] =v1.w;
            xv[8]=v2.x; xv[9]=v2.y; xv[10]=v2.z; xv[11]=v2.w;
        } else {                                 // first block, warp 0: clamp low
            const int xb = bA - 8;
            #pragma unroll
            for (int j = 0; j < 12; j++) {
                int g = xb + j;
                xv[j] = xrow[g < 0 ? 0 : g];
            }
        }
        #pragma unroll
        for (int k = 0; k < 4; k++) {
            float ue =      uf2[11] * xv[k + 2];
            ue = fmaf(uf2[9],  xv[k + 3], ue);
            ue = fmaf(uf2[7],  xv[k + 4], ue);
            ue = fmaf(uf2[5],  xv[k + 5], ue);
            ue = fmaf(uf2[3],  xv[k + 6], ue);
            ue = fmaf(uf2[1],  xv[k + 7], ue);
            float uo =      uf2[10] * xv[k + 3];
            uo = fmaf(uf2[8],  xv[k + 4], uo);
            uo = fmaf(uf2[6],  xv[k + 5], uo);
            uo = fmaf(uf2[4],  xv[k + 6], uo);
            uo = fmaf(uf2[2],  xv[k + 7], uo);
            uo = fmaf(uf2[0],  xv[k + 8], uo);
            evA[k] = snake(ue, a2, c0);
            ovA[k] = snake(uo, a2, c0);
        }
        // first block, tid 0: act indices t<0 clamp to act[0] == E[3]
        if (first && tid == 0) {
            evA[0] = evA[1] = evA[2] = evA[3];
            ovA[0] = ovA[1] = ovA[2] = evA[3];
        }
        *(float4*)(Es + bA) = make_float4(evA[0], evA[1], evA[2], evA[3]);
        *(float4*)(Os + bA) = make_float4(ovA[0], ovA[1], ovA[2], ovA[3]);
    }

    // ================= phase 1, chunk B (pairs bB..bB+3) =================
    {
        float xv[12];
        {   // chunk B never touches row edges: base >= m0+1016, top <= m0+2047
            const float4* s = (const float4*)(xrow + (m0 + bB - 8));
            float4 v0 = s[0], v1 = s[1], v2 = s[2];
            xv[0]=v0.x; xv[1]=v0.y; xv[2] =v0.z; xv[3] =v0.w;
            xv[4]=v1.x; xv[5]=v1.y; xv[6] =v1.z; xv[7] =v1.w;
            xv[8]=v2.x; xv[9]=v2.y; xv[10]=v2.z; xv[11]=v2.w;
        }
        #pragma unroll
        for (int k = 0; k < 4; k++) {
            float ue =      uf2[11] * xv[k + 2];
            ue = fmaf(uf2[9],  xv[k + 3], ue);
            ue = fmaf(uf2[7],  xv[k + 4], ue);
            ue = fmaf(uf2[5],  xv[k + 5], ue);
            ue = fmaf(uf2[3],  xv[k + 6], ue);
            ue = fmaf(uf2[1],  xv[k + 7], ue);
            float uo =      uf2[10] * xv[k + 3];
            uo = fmaf(uf2[8],  xv[k + 4], uo);
            uo = fmaf(uf2[6],  xv[k + 5], uo);
            uo = fmaf(uf2[4],  xv[k + 6], uo);
            uo = fmaf(uf2[2],  xv[k + 7], uo);
            uo = fmaf(uf2[0],  xv[k + 8], uo);
            evB[k] = snake(ue, a2, c0);
            ovB[k] = snake(uo, a2, c0);
        }
        *(float4*)(Es + bB) = make_float4(evB[0], evB[1], evB[2], evB[3]);
        *(float4*)(Os + bB) = make_float4(ovB[0], ovB[1], ovB[2], ovB[3]);
    }

    // ---- halo pairs q = TILE..TILE+5 (scalar, clamped global reads) ----
    if (tid < 6) {
        const int q = TILE + tid;
        float xh[7];
        #pragma unroll
        for (int j = 0; j < 7; j++) {
            int g = m0 + q - 6 + j;
            xh[j] = xrow[g > TLEN - 1 ? TLEN - 1 : g];
        }
        float ue =      uf2[11] * xh[0];
        ue = fmaf(uf2[9],  xh[1], ue);
        ue = fmaf(uf2[7],  xh[2], ue);
        ue = fmaf(uf2[5],  xh[3], ue);
        ue = fmaf(uf2[3],  xh[4], ue);
        ue = fmaf(uf2[1],  xh[5], ue);
        float uo =      uf2[10] * xh[1];
        uo = fmaf(uf2[8],  xh[2], uo);
        uo = fmaf(uf2[6],  xh[3], uo);
        uo = fmaf(uf2[4],  xh[4], uo);
        uo = fmaf(uf2[2],  xh[5], uo);
        uo = fmaf(uf2[0],  xh[6], uo);
        float Eh = snake(ue, a2, c0);
        float Oh = snake(uo, a2, c0);
        if (last) {
            // t > 16383 clamps to act[16383] == O[TILE+2]
            if (tid == 2) {
                Es[q] = Eh; Os[q] = Oh;
                Es[TILE+3] = Oh; Es[TILE+4] = Oh; Es[TILE+5] = Oh;
                Os[TILE+3] = Oh; Os[TILE+4] = Oh; Os[TILE+5] = Oh;
            } else if (tid < 2) {
                Es[q] = Eh; Os[q] = Oh;
            }
        } else {
            Es[q] = Eh; Os[q] = Oh;
        }
    }
    __syncthreads();

    // ================= phase 2 =================
    float df[12];
    {
        const float4* d4 = (const float4*)dnf;
        float4 d0 = __ldg(d4), d1 = __ldg(d4 + 1), d2 = __ldg(d4 + 2);
        df[0] = d0.x; df[1] = d0.y; df[2]  = d0.z; df[3]  = d0.w;
        df[4] = d1.x; df[5] = d1.y; df[6]  = d1.z; df[7]  = d1.w;
        df[8] = d2.x; df[9] = d2.y; df[10] = d2.z; df[11] = d2.w;
    }

    // chunk A outputs
    {
        float o[9], e[10];
        o[0] = ovA[0]; o[1] = ovA[1]; o[2] = ovA[2]; o[3] = ovA[3];
        e[1] = evA[1]; e[2] = evA[2]; e[3] = evA[3];
        float4 o4 = *(const float4*)(Os + bA + 4);
        o[4] = o4.x; o[5] = o4.y; o[6] = o4.z; o[7] = o4.w;
        o[8] = Os[bA + 8];
        float4 e4 = *(const float4*)(Es + bA + 4);
        e[4] = e4.x; e[5] = e4.y; e[6] = e4.z; e[7] = e4.w;
        float2 e89 = *(const float2*)(Es + bA + 8);
        e[8] = e89.x; e[9] = e89.y;

        float4 r4;
        #pragma unroll
        for (int k = 0; k < 4; k++) {
            float r = df[0] * o[k];
            r = fmaf(df[1],  e[k + 1], r);
            r = fmaf(df[2],  o[k + 1], r);
            r = fmaf(df[3],  e[k + 2], r);
            r = fmaf(df[4],  o[k + 2], r);
            r = fmaf(df[5],  e[k + 3], r);
            r = fmaf(df[6],  o[k + 3], r);
            r = fmaf(df[7],  e[k + 4], r);
            r = fmaf(df[8],  o[k + 4], r);
            r = fmaf(df[9],  e[k + 5], r);
            r = fmaf(df[10], o[k + 5], r);
            r = fmaf(df[11], e[k + 6], r);
            ((float*)&r4)[k] = r;
        }
        *(float4*)(out + (size_t)row * TLEN + m0 + bA) = r4;
    }

    // chunk B outputs
    {
        float o[9], e[10];
        o[0] = ovB[0]; o[1] = ovB[1]; o[2] = ovB[2]; o[3] = ovB[3];
        e[1] = evB[1]; e[2] = evB[2]; e[3] = evB[3];
        float4 o4 = *(const float4*)(Os + bB + 4);
        o[4] = o4.x; o[5] = o4.y; o[6] = o4.z; o[7] = o4.w;
        o[8] = Os[bB + 8];
        float4 e4 = *(const float4*)(Es + bB + 4);
        e[4] = e4.x; e[5] = e4.y; e[6] = e4.z; e[7] = e4.w;
        float2 e89 = *(const float2*)(Es + bB + 8);
        e[8] = e89.x; e[9] = e89.y;

        float4 r4;
        #pragma unroll
        for (int k = 0; k < 4; k++) {
            float r = df[0] * o[k];
            r = fmaf(df[1],  e[k + 1], r);
            r = fmaf(df[2],  o[k + 1], r);
            r = fmaf(df[3],  e[k + 2], r);
            r = fmaf(df[4],  o[k + 2], r);
            r = fmaf(df[5],  e[k + 3], r);
            r = fmaf(df[6],  o[k + 3], r);
            r = fmaf(df[7],  e[k + 4], r);
            r = fmaf(df[8],  o[k + 4], r);
            r = fmaf(df[9],  e[k + 5], r);
            r = fmaf(df[10], o[k + 5], r);
            r = fmaf(df[11], e[k + 6], r);
            ((float*)&r4)[k] = r;
        }
        *(float4*)(out + (size_t)row * TLEN + m0 + bB) = r4;
    }
}

extern "C" void kernel_launch(void* const* d_in, const int* in_sizes, int n_in,
                              void* d_out, int out_size) {
    const float* x     = (const float*)d_in[0];
    const float* upf   = (const float*)d_in[1];
    const float* dnf   = (const float*)d_in[2];
    const float* alpha = (const float*)d_in[3];
    const float* beta  = (const float*)d_in[4];
    float* out = (float*)d_out;

    const int rows = in_sizes[0] / TLEN;   // B*C
    const int nch  = in_sizes[3];          // C

    dim3 grid(TLEN / TILE, rows);
    act1d_kernel<<<grid, NTHR>>>(x, upf, dnf, alpha, beta, out, nch);
}

// round 7
// speedup vs baseline: 1.3520x; 1.1066x over previous
#include <cuda_runtime.h>

#define TLEN 8192
#define TILE 2048            // outputs per block
#define NTHR 256             // 2 chunks of 4 outputs per thread
#define NEO  2056            // 2054 act pairs used + pad

// snake(u) = u + ib*sin^2(a*u) = (u + c0) - c0*cos(2a*u),  c0 = ib/2
__device__ __forceinline__ float snake(float u, float a2, float c0) {
    return fmaf(-c0, __cosf(u * a2), u + c0);
}

__global__ void __launch_bounds__(NTHR, 6)
act1d_kernel(const float* __restrict__ x,
             const float* __restrict__ upf,
             const float* __restrict__ dnf,
             const float* __restrict__ alpha,
             const float* __restrict__ beta,
             float* __restrict__ out,
             int nch)
{
    __shared__ __align__(16) float Es[NEO];
    __shared__ __align__(16) float Os[NEO];

    const int tid = threadIdx.x;
    const int row = blockIdx.y;
    const int m0  = blockIdx.x * TILE;
    const int ch  = row % nch;
    const int bA  = 4 * tid;             // chunk A pairs/outputs
    const int bB  = 1024 + 4 * tid;      // chunk B pairs/outputs

    const float a2 = 2.0f * __expf(__ldg(alpha + ch));
    const float k0 = 0.5f * __fdividef(1.0f, __expf(__ldg(beta + ch)) + 1e-9f);

    const float* xrow = x + (size_t)row * TLEN;
    const bool first = (m0 == 0);
    const bool last  = (m0 + TILE == TLEN);

    // Kaiser-sinc filter is symmetric: uf[j] == uf[11-j].
    // E taps (uf[11,9,7,5,3,1]) and O taps (uf[10,8,6,4,2,0]) are the SAME
    // 6-coeff set c[i] = 2*uf[2i+1], applied in opposite order.
    float c[6];
    {
        const float4* u4 = (const float4*)upf;
        float4 u0 = __ldg(u4), u1 = __ldg(u4 + 1), u2 = __ldg(u4 + 2);
        c[0] = 2.f * u0.y;   // uf[1]  == uf[10]
        c[1] = 2.f * u0.w;   // uf[3]  == uf[8]
        c[2] = 2.f * u1.y;   // uf[5]  == uf[6]
        c[3] = 2.f * u1.w;   // uf[7]  == uf[4]
        c[4] = 2.f * u2.y;   // uf[9]  == uf[2]
        c[5] = 2.f * u2.w;   // uf[11] == uf[0]
    }

    float evA[4], ovA[4], evB[4], ovB[4];

    // ================= phase 1, chunk A (pairs bA..bA+3) =================
    {
        float xv[12];
        if (!(first && tid < 32)) {              // warp-uniform
            const float4* s = (const float4*)(xrow + (m0 + bA - 8));
            float4 v0 = s[0], v1 = s[1], v2 = s[2];
            xv[0]=v0.x; xv[1]=v0.y; xv[2] =v0.z; xv[3] =v0.w;
            xv[4]=v1.x; xv[5]=v1.y; xv[6] =v1.z; xv[7] =v1.w;
            xv[8]=v2.x; xv[9]=v2.y; xv[10]=v2.z; xv[11]=v2.w;
        } else {                                 // first block, warp 0: clamp low
            const int xb = bA - 8;
            #pragma unroll
            for (int j = 0; j < 12; j++) {
                int g = xb + j;
                xv[j] = xrow[g < 0 ? 0 : g];
            }
        }
        #pragma unroll
        for (int k = 0; k < 4; k++) {
            float ue =      c[5] * xv[k + 2];
            ue = fmaf(c[4], xv[k + 3], ue);
            ue = fmaf(c[3], xv[k + 4], ue);
            ue = fmaf(c[2], xv[k + 5], ue);
            ue = fmaf(c[1], xv[k + 6], ue);
            ue = fmaf(c[0], xv[k + 7], ue);
            float uo =      c[0] * xv[k + 3];
            uo = fmaf(c[1], xv[k + 4], uo);
            uo = fmaf(c[2], xv[k + 5], uo);
            uo = fmaf(c[3], xv[k + 6], uo);
            uo = fmaf(c[4], xv[k + 7], uo);
            uo = fmaf(c[5], xv[k + 8], uo);
            evA[k] = snake(ue, a2, k0);
            ovA[k] = snake(uo, a2, k0);
        }
        // first block, tid 0: act indices t<0 clamp to act[0] == E[3]
        if (first && tid == 0) {
            evA[0] = evA[1] = evA[2] = evA[3];
            ovA[0] = ovA[1] = ovA[2] = evA[3];
        }
        *(float4*)(Es + bA) = make_float4(evA[0], evA[1], evA[2], evA[3]);
        *(float4*)(Os + bA) = make_float4(ovA[0], ovA[1], ovA[2], ovA[3]);
    }

    // ================= phase 1, chunk B (pairs bB..bB+3) =================
    {
        float xv[12];
        {   // chunk B never touches row edges
            const float4* s = (const float4*)(xrow + (m0 + bB - 8));
            float4 v0 = s[0], v1 = s[1], v2 = s[2];
            xv[0]=v0.x; xv[1]=v0.y; xv[2] =v0.z; xv[3] =v0.w;
            xv[4]=v1.x; xv[5]=v1.y; xv[6] =v1.z; xv[7] =v1.w;
            xv[8]=v2.x; xv[9]=v2.y; xv[10]=v2.z; xv[11]=v2.w;
        }
        #pragma unroll
        for (int k = 0; k < 4; k++) {
            float ue =      c[5] * xv[k + 2];
            ue = fmaf(c[4], xv[k + 3], ue);
            ue = fmaf(c[3], xv[k + 4], ue);
            ue = fmaf(c[2], xv[k + 5], ue);
            ue = fmaf(c[1], xv[k + 6], ue);
            ue = fmaf(c[0], xv[k + 7], ue);
            float uo =      c[0] * xv[k + 3];
            uo = fmaf(c[1], xv[k + 4], uo);
            uo = fmaf(c[2], xv[k + 5], uo);
            uo = fmaf(c[3], xv[k + 6], uo);
            uo = fmaf(c[4], xv[k + 7], uo);
            uo = fmaf(c[5], xv[k + 8], uo);
            evB[k] = snake(ue, a2, k0);
            ovB[k] = snake(uo, a2, k0);
        }
        *(float4*)(Es + bB) = make_float4(evB[0], evB[1], evB[2], evB[3]);
        *(float4*)(Os + bB) = make_float4(ovB[0], ovB[1], ovB[2], ovB[3]);
    }

    // ---- halo pairs q = TILE..TILE+5 (scalar, clamped global reads) ----
    if (tid < 6) {
        const int q = TILE + tid;
        float xh[7];
        #pragma unroll
        for (int j = 0; j < 7; j++) {
            int g = m0 + q - 6 + j;
            xh[j] = xrow[g > TLEN - 1 ? TLEN - 1 : g];
        }
        float ue =      c[5] * xh[0];
        ue = fmaf(c[4], xh[1], ue);
        ue = fmaf(c[3], xh[2], ue);
        ue = fmaf(c[2], xh[3], ue);
        ue = fmaf(c[1], xh[4], ue);
        ue = fmaf(c[0], xh[5], ue);
        float uo =      c[0] * xh[1];
        uo = fmaf(c[1], xh[2], uo);
        uo = fmaf(c[2], xh[3], uo);
        uo = fmaf(c[3], xh[4], uo);
        uo = fmaf(c[4], xh[5], uo);
        uo = fmaf(c[5], xh[6], uo);
        float Eh = snake(ue, a2, k0);
        float Oh = snake(uo, a2, k0);
        if (last) {
            // t > 16383 clamps to act[16383] == O[TILE+2]
            if (tid == 2) {
                Es[q] = Eh; Os[q] = Oh;
                Es[TILE+3] = Oh; Es[TILE+4] = Oh; Es[TILE+5] = Oh;
                Os[TILE+3] = Oh; Os[TILE+4] = Oh; Os[TILE+5] = Oh;
            } else if (tid < 2) {
                Es[q] = Eh; Os[q] = Oh;
            }
        } else {
            Es[q] = Eh; Os[q] = Oh;
        }
    }
    __syncthreads();

    // ================= phase 2 =================
    // down filter symmetric too: df[j] == df[11-j]; keep d[0..5]
    float d[6];
    {
        const float4* d4 = (const float4*)dnf;
        float4 dd0 = __ldg(d4), dd1 = __ldg(d4 + 1);
        d[0] = dd0.x; d[1] = dd0.y; d[2] = dd0.z;
        d[3] = dd0.w; d[4] = dd1.x; d[5] = dd1.y;
    }

    // out[m0+b+k] = sum_{r} df[2r]*O[b+k+r] + df[2r+1]*E[b+k+r+1]
    //             = d0*o[k]   + d1*e[k+1] + d2*o[k+1] + d3*e[k+2] + d4*o[k+2] + d5*e[k+3]
    //             + d5*o[k+3] + d4*e[k+4] + d3*o[k+4] + d2*e[k+5] + d1*o[k+5] + d0*e[k+6]
    // chunk A outputs
    {
        float o[9], e[10];
        o[0] = ovA[0]; o[1] = ovA[1]; o[2] = ovA[2]; o[3] = ovA[3];
        e[1] = evA[1]; e[2] = evA[2]; e[3] = evA[3];
        float4 o4 = *(const float4*)(Os + bA + 4);
        o[4] = o4.x; o[5] = o4.y; o[6] = o4.z; o[7] = o4.w;
        o[8] = Os[bA + 8];
        float4 e4 = *(const float4*)(Es + bA + 4);
        e[4] = e4.x; e[5] = e4.y; e[6] = e4.z; e[7] = e4.w;
        float2 e89 = *(const float2*)(Es + bA + 8);
        e[8] = e89.x; e[9] = e89.y;

        float4 r4;
        #pragma unroll
        for (int k = 0; k < 4; k++) {
            float r = d[0] * o[k];
            r = fmaf(d[1], e[k + 1], r);
            r = fmaf(d[2], o[k + 1], r);
            r = fmaf(d[3], e[k + 2], r);
            r = fmaf(d[4], o[k + 2], r);
            r = fmaf(d[5], e[k + 3], r);
            r = fmaf(d[5], o[k + 3], r);
            r = fmaf(d[4], e[k + 4], r);
            r = fmaf(d[3], o[k + 4], r);
            r = fmaf(d[2], e[k + 5], r);
            r = fmaf(d[1], o[k + 5], r);
            r = fmaf(d[0], e[k + 6], r);
            ((float*)&r4)[k] = r;
        }
        *(float4*)(out + (size_t)row * TLEN + m0 + bA) = r4;
    }

    // chunk B outputs
    {
        float o[9], e[10];
        o[0] = ovB[0]; o[1] = ovB[1]; o[2] = ovB[2]; o[3] = ovB[3];
        e[1] = evB[1]; e[2] = evB[2]; e[3] = evB[3];
        float4 o4 = *(const float4*)(Os + bB + 4);
        o[4] = o4.x; o[5] = o4.y; o[6] = o4.z; o[7] = o4.w;
        o[8] = Os[bB + 8];
        float4 e4 = *(const float4*)(Es + bB + 4);
        e[4] = e4.x; e[5] = e4.y; e[6] = e4.z; e[7] = e4.w;
        float2 e89 = *(const float2*)(Es + bB + 8);
        e[8] = e89.x; e[9] = e89.y;

        float4 r4;
        #pragma unroll
        for (int k = 0; k < 4; k++) {
            float r = d[0] * o[k];
            r = fmaf(d[1], e[k + 1], r);
            r = fmaf(d[2], o[k + 1], r);
            r = fmaf(d[3], e[k + 2], r);
            r = fmaf(d[4], o[k + 2], r);
            r = fmaf(d[5], e[k + 3], r);
            r = fmaf(d[5], o[k + 3], r);
            r = fmaf(d[4], e[k + 4], r);
            r = fmaf(d[3], o[k + 4], r);
            r = fmaf(d[2], e[k + 5], r);
            r = fmaf(d[1], o[k + 5], r);
            r = fmaf(d[0], e[k + 6], r);
            ((float*)&r4)[k] = r;
        }
        *(float4*)(out + (size_t)row * TLEN + m0 + bB) = r4;
    }
}

extern "C" void kernel_launch(void* const* d_in, const int* in_sizes, int n_in,
                              void* d_out, int out_size) {
    const float* x     = (const float*)d_in[0];
    const float* upf   = (const float*)d_in[1];
    const float* dnf   = (const float*)d_in[2];
    const float* alpha = (const float*)d_in[3];
    const float* beta  = (const float*)d_in[4];
    float* out = (float*)d_out;

    const int rows = in_sizes[0] / TLEN;   // B*C
    const int nch  = in_sizes[3];          // C

    dim3 grid(TLEN / TILE, rows);
    act1d_kernel<<<grid, NTHR>>>(x, upf, dnf, alpha, beta, out, nch);
}